// round 6
// baseline (speedup 1.0000x reference)
#include <cuda_runtime.h>
#include <cuda_bf16.h>
#include <math.h>

// Problem constants
#define TSEQ 512
#define BATCH 128
#define DIMD 256
#define HID 128
#define G4 512      // 4*H
#define LBL 4

typedef unsigned long long u64;

// ---------------- scratch (device globals; no allocation allowed) ----------------
__device__ float d_Xg[(size_t)2 * TSEQ * BATCH * G4];      // 268 MB: input gates + biases, [dir][t][b][512]
__device__ float d_hbuf[(size_t)TSEQ * BATCH * 2 * HID];   // 67 MB: [t][b][256] = concat(hf, hb)
__device__ float d_scores[(size_t)TSEQ * BATCH * LBL];     // 1 MB:  [t][b][4]
__device__ unsigned d_btbuf[(size_t)TSEQ * BATCH];         // 256 KB: packed backtrace (2 bits/label)

// ---------------- f32x2 packed math (register-only packing) ----------------
__device__ __forceinline__ u64 pack2(float x, float y) {
    u64 r; asm("mov.b64 %0, {%1,%2};" : "=l"(r) : "f"(x), "f"(y)); return r;
}
__device__ __forceinline__ float2 unpack2(u64 a) {
    float x, y; asm("mov.b64 {%0,%1}, %2;" : "=f"(x), "=f"(y) : "l"(a));
    return make_float2(x, y);
}
__device__ __forceinline__ void fma2(u64& d, u64 a, u64 b) {
    asm("fma.rn.f32x2 %0, %1, %2, %0;" : "+l"(d) : "l"(a), "l"(b));
}

__device__ __forceinline__ float sigm(float x) { return 1.f / (1.f + expf(-x)); }

// ============================================================================
// Kernel 1: embedding gather + Xg = x @ W_ih^T + (b_ih + b_hh), both directions
// Grid (512 m-tiles = timesteps, 8 n-tiles: 4 fwd + 4 bwd), 256 threads.
// Tile 128x128, K=256, packed f32x2 FMA (2x fp32 rate on sm_103a).
// ============================================================================
__global__ void __launch_bounds__(256) k_gemm(
    const int* __restrict__ pad_seq, const float* __restrict__ emb,
    const float* __restrict__ Wihf, const float* __restrict__ Wihb,
    const float* __restrict__ bihf, const float* __restrict__ bhhf,
    const float* __restrict__ bihb, const float* __restrict__ bhhb)
{
    __shared__ float As[16][128];   // [k][m]  m = batch row
    __shared__ float Bs[16][128];   // [k][n]  n = gate row
    __shared__ int   tok[128];

    const int tid = threadIdx.x;
    const int mt  = blockIdx.x;          // timestep t
    const int nt  = blockIdx.y;          // 0..7
    const int dir = nt >> 2;
    const int gbase = (nt & 3) * 128;    // gate column base within direction
    const float* __restrict__ W = dir ? Wihb : Wihf;

    if (tid < 128) tok[tid] = pad_seq[tid * TSEQ + mt];   // pad_seq[b][t]

    const int tx = tid & 15, ty = tid >> 4;
    u64 acc[8][4];
#pragma unroll
    for (int i = 0; i < 8; ++i)
#pragma unroll
        for (int p = 0; p < 4; ++p) acc[i][p] = pack2(0.f, 0.f);

    __syncthreads();

    for (int kt = 0; kt < 16; ++kt) {
        const int k0 = kt * 16;
        for (int e = tid; e < 512; e += 256) {
            const int row = e >> 2;            // 0..127
            const int kq  = (e & 3) * 4;       // 0,4,8,12
            const float4 av = *reinterpret_cast<const float4*>(
                &emb[(size_t)tok[row] * DIMD + k0 + kq]);
            As[kq + 0][row] = av.x; As[kq + 1][row] = av.y;
            As[kq + 2][row] = av.z; As[kq + 3][row] = av.w;
            const float4 bv = *reinterpret_cast<const float4*>(
                &W[(size_t)(gbase + row) * DIMD + k0 + kq]);
            Bs[kq + 0][row] = bv.x; Bs[kq + 1][row] = bv.y;
            Bs[kq + 2][row] = bv.z; Bs[kq + 3][row] = bv.w;
        }
        __syncthreads();
#pragma unroll
        for (int kk = 0; kk < 16; ++kk) {
            const float4 a0 = *reinterpret_cast<const float4*>(&As[kk][ty * 8]);
            const float4 a1 = *reinterpret_cast<const float4*>(&As[kk][ty * 8 + 4]);
            const float4 w0 = *reinterpret_cast<const float4*>(&Bs[kk][tx * 8]);
            const float4 w1 = *reinterpret_cast<const float4*>(&Bs[kk][tx * 8 + 4]);
            const u64 b0 = pack2(w0.x, w0.y);   // natural reg pair -> folds
            const u64 b1 = pack2(w0.z, w0.w);
            const u64 b2 = pack2(w1.x, w1.y);
            const u64 b3 = pack2(w1.z, w1.w);
            const float ar[8] = {a0.x, a0.y, a0.z, a0.w, a1.x, a1.y, a1.z, a1.w};
#pragma unroll
            for (int i = 0; i < 8; ++i) {
                const u64 ai = pack2(ar[i], ar[i]);   // 1 MOV per i
                fma2(acc[i][0], ai, b0);
                fma2(acc[i][1], ai, b1);
                fma2(acc[i][2], ai, b2);
                fma2(acc[i][3], ai, b3);
            }
        }
        __syncthreads();
    }

    // epilogue: add (b_ih + b_hh)
    const float* bi = dir ? bihb : bihf;
    const float* bh = dir ? bhhb : bhhf;
    float bias[8];
#pragma unroll
    for (int jj = 0; jj < 8; ++jj) {
        const int g = gbase + tx * 8 + jj;
        bias[jj] = bi[g] + bh[g];
    }
#pragma unroll
    for (int i = 0; i < 8; ++i) {
        const int brow = ty * 8 + i;   // batch index
        float* o = d_Xg + (size_t)dir * ((size_t)TSEQ * BATCH * G4)
                 + (size_t)mt * (BATCH * G4) + (size_t)brow * G4 + gbase + tx * 8;
        const float2 v0 = unpack2(acc[i][0]);
        const float2 v1 = unpack2(acc[i][1]);
        const float2 v2 = unpack2(acc[i][2]);
        const float2 v3 = unpack2(acc[i][3]);
        float4 o0 = {v0.x + bias[0], v0.y + bias[1], v1.x + bias[2], v1.y + bias[3]};
        float4 o1 = {v2.x + bias[4], v2.y + bias[5], v3.x + bias[6], v3.y + bias[7]};
        *reinterpret_cast<float4*>(o)     = o0;
        *reinterpret_cast<float4*>(o + 4) = o1;
    }
}

// ============================================================================
// Kernel 2: bidirectional LSTM recurrence. One block per batch element.
// 512 threads: thread j owns gate row j of W_hh [512,128].
// Weight split: cols 0..95 in registers (48 packed u64), cols 96..127 in
// shared (16 u64-slots x 512 = 64 KB). h pairs come straight from LDS.128
// (float4) — both f32x2 operands are natural pairs, zero dup-movs.
// Per step: g_j = Xg_j + sum_k Whh[j][k]*h[k]; threads <128 run activations.
// ============================================================================
__global__ void __launch_bounds__(512, 1) k_lstm(
    const int* __restrict__ lens,
    const float* __restrict__ Whhf, const float* __restrict__ Whhb)
{
    extern __shared__ char smp[];
    u64*   ws  = reinterpret_cast<u64*>(smp);                 // 16*512 u64 = 65536 B
    float* h_s = reinterpret_cast<float*>(smp + 65536);       // 128 floats
    float* g_s = reinterpret_cast<float*>(smp + 65536 + 512); // 512 floats

    const int j = threadIdx.x;
    const int b = blockIdx.x;
    const int len = lens[b];

    for (int dir = 0; dir < 2; ++dir) {
        const float* __restrict__ wrow = (dir ? Whhb : Whhf) + (size_t)j * HID;
        u64 wr[48];
#pragma unroll
        for (int p = 0; p < 48; ++p) {
            const float2 w = *reinterpret_cast<const float2*>(wrow + 2 * p);
            wr[p] = pack2(w.x, w.y);                          // cols 0..95
        }
#pragma unroll
        for (int p = 0; p < 16; ++p) {
            const float2 w = *reinterpret_cast<const float2*>(wrow + 96 + 2 * p);
            ws[p * 512 + j] = pack2(w.x, w.y);                // cols 96..127
        }
        if (j < HID) h_s[j] = 0.f;
        float c = 0.f;
        __syncthreads();

        const float* xgb = d_Xg + (size_t)dir * ((size_t)TSEQ * BATCH * G4)
                         + (size_t)b * G4 + j;
        int t = dir ? (TSEQ - 1) : 0;
        const int stp = dir ? -1 : 1;
        float xg = xgb[(size_t)t * (BATCH * G4)];

        for (int it = 0; it < TSEQ; ++it) {
            const int tn = t + stp;
            float xgn = 0.f;
            if (it < TSEQ - 1) xgn = xgb[(size_t)tn * (BATCH * G4)];   // prefetch

            u64 acc = pack2(xg, 0.f);
            const float4* h4 = reinterpret_cast<const float4*>(h_s);
#pragma unroll
            for (int q = 0; q < 24; ++q) {          // cols 0..95 from registers
                const float4 hv = h4[q];
                fma2(acc, wr[2 * q],     pack2(hv.x, hv.y));
                fma2(acc, wr[2 * q + 1], pack2(hv.z, hv.w));
            }
#pragma unroll
            for (int q = 0; q < 8; ++q) {           // cols 96..127 from shared
                const float4 hv = h4[24 + q];
                fma2(acc, ws[(2 * q) * 512 + j],     pack2(hv.x, hv.y));
                fma2(acc, ws[(2 * q + 1) * 512 + j], pack2(hv.z, hv.w));
            }
            const float2 av = unpack2(acc);
            g_s[j] = av.x + av.y;
            __syncthreads();

            if (j < HID) {
                const float gi = g_s[j];
                const float gf = g_s[j + 128];
                const float gc = g_s[j + 256];
                const float go = g_s[j + 384];
                const float i_ = sigm(gi);
                const float f_ = sigm(gf);
                const float o_ = sigm(go);
                const float c2 = f_ * c + i_ * tanhf(gc);
                const float h2 = o_ * tanhf(c2);
                const bool m = (t < len);
                d_hbuf[((size_t)t * BATCH + b) * (2 * HID) + dir * HID + j] = m ? h2 : 0.f;
                if (m) { c = c2; h_s[j] = h2; }
            }
            __syncthreads();
            xg = xgn;
            t = tn;
        }
        __syncthreads();   // protect ws/h_s reinit for next direction
    }
}

// ============================================================================
// Kernel 3: emissions  scores[t][b][l] = h[t][b][:] @ W_lab[l][:] + b_lab[l]
// (unchanged from passing R5 version)
// ============================================================================
__global__ void __launch_bounds__(256) k_emis(
    const float* __restrict__ Wlab, const float* __restrict__ blab)
{
    __shared__ float wl[LBL * DIMD];
    const int tid = threadIdx.x;
    for (int e = tid; e < LBL * DIMD; e += 256) wl[e] = Wlab[e];
    __syncthreads();

    const int wid = tid >> 5, lane = tid & 31;
    const int m = blockIdx.x * 8 + wid;        // m = t*128 + b
    const float* h = d_hbuf + (size_t)m * (2 * HID);

    float a0 = 0.f, a1 = 0.f, a2 = 0.f, a3 = 0.f;
#pragma unroll
    for (int cch = 0; cch < 2; ++cch) {
        const int k = cch * 128 + lane * 4;
        const float4 hv = *reinterpret_cast<const float4*>(h + k);
        a0 += hv.x * wl[k]       + hv.y * wl[k + 1]       + hv.z * wl[k + 2]       + hv.w * wl[k + 3];
        a1 += hv.x * wl[256 + k] + hv.y * wl[256 + k + 1] + hv.z * wl[256 + k + 2] + hv.w * wl[256 + k + 3];
        a2 += hv.x * wl[512 + k] + hv.y * wl[512 + k + 1] + hv.z * wl[512 + k + 2] + hv.w * wl[512 + k + 3];
        a3 += hv.x * wl[768 + k] + hv.y * wl[768 + k + 1] + hv.z * wl[768 + k + 2] + hv.w * wl[768 + k + 3];
    }
#pragma unroll
    for (int off = 16; off; off >>= 1) {
        a0 += __shfl_down_sync(0xffffffffu, a0, off);
        a1 += __shfl_down_sync(0xffffffffu, a1, off);
        a2 += __shfl_down_sync(0xffffffffu, a2, off);
        a3 += __shfl_down_sync(0xffffffffu, a3, off);
    }
    if (lane == 0) {
        float4 o = {a0 + blab[0], a1 + blab[1], a2 + blab[2], a3 + blab[3]};
        *reinterpret_cast<float4*>(d_scores + (size_t)m * 4) = o;
    }
}

// ============================================================================
// Kernel 4: Viterbi forward + backtrace (unchanged from passing R5 version).
// ============================================================================
__global__ void __launch_bounds__(128) k_vit(
    const int* __restrict__ lens, const float* __restrict__ trans,
    const float* __restrict__ fromB, const float* __restrict__ toE,
    float* __restrict__ out)
{
    __shared__ float tr[16], fb[4], te[4];
    const int b = threadIdx.x;
    if (b < 16) tr[b] = trans[b];
    if (b < 4) { fb[b] = fromB[b]; te[b] = toE[b]; }
    __syncthreads();

    const int len = lens[b];
    const float4* sc = reinterpret_cast<const float4*>(d_scores);  // sc[t*128+b]

    const float4 e0 = sc[b];
    float best[4] = {fb[0] + e0.x, fb[1] + e0.y, fb[2] + e0.z, fb[3] + e0.w};

    // ---- forward ----
    for (int tc = 1; tc < TSEQ; tc += 8) {
        float4 eb[8];
#pragma unroll
        for (int u = 0; u < 8; ++u) {
            const int t = tc + u;
            if (t < TSEQ) eb[u] = sc[t * BATCH + b];
        }
#pragma unroll
        for (int u = 0; u < 8; ++u) {
            const int t = tc + u;
            if (t < TSEQ) {
                const float e[4] = {eb[u].x, eb[u].y, eb[u].z, eb[u].w};
                unsigned w = 0;
                float nb[4];
#pragma unroll
                for (int l = 0; l < 4; ++l) {
                    float mx = best[0] + tr[l];
                    int ar = 0;
#pragma unroll
                    for (int p = 1; p < 4; ++p) {
                        const float v = best[p] + tr[p * 4 + l];
                        if (v > mx) { mx = v; ar = p; }
                    }
                    nb[l] = mx + e[l];
                    w |= (unsigned)ar << (2 * l);
                }
                d_btbuf[t * BATCH + b] = w;
                if (t < len) { best[0] = nb[0]; best[1] = nb[1]; best[2] = nb[2]; best[3] = nb[3]; }
            }
        }
    }

    // ---- terminal ----
    const float fv[4] = {best[0] + te[0], best[1] + te[1], best[2] + te[2], best[3] + te[3]};
    int last = 0; float bm = fv[0];
#pragma unroll
    for (int l = 1; l < 4; ++l) if (fv[l] > bm) { bm = fv[l]; last = l; }

    // ---- backtrace (descending, prefetched) ----
    int lab = last;
    float* ob = out + (size_t)b * TSEQ;
    for (int tc = TSEQ - 1; tc >= 0; tc -= 8) {
        unsigned wbuf[8];
#pragma unroll
        for (int u = 0; u < 8; ++u) {
            const int t = tc - u;
            wbuf[u] = (t >= 0 && t < TSEQ - 1) ? d_btbuf[(t + 1) * BATCH + b] : 0u;
        }
#pragma unroll
        for (int u = 0; u < 8; ++u) {
            const int t = tc - u;
            if (t >= 0) {
                int v;
                if (t >= len) v = 0;
                else if (t == len - 1) { lab = last; v = lab; }
                else { lab = (int)((wbuf[u] >> (2 * lab)) & 3u); v = lab; }
                ob[t] = (float)v;   // float32 output
            }
        }
    }
}

// ============================================================================
extern "C" void kernel_launch(void* const* d_in, const int* in_sizes, int n_in,
                              void* d_out, int out_size)
{
    const int*   pad_seq = (const int*)  d_in[0];
    const int*   lens    = (const int*)  d_in[1];
    const float* emb     = (const float*)d_in[2];
    const float* Wihf    = (const float*)d_in[3];
    const float* Whhf    = (const float*)d_in[4];
    const float* bihf    = (const float*)d_in[5];
    const float* bhhf    = (const float*)d_in[6];
    const float* Wihb    = (const float*)d_in[7];
    const float* Whhb    = (const float*)d_in[8];
    const float* bihb    = (const float*)d_in[9];
    const float* bhhb    = (const float*)d_in[10];
    const float* Wlab    = (const float*)d_in[11];
    const float* blab    = (const float*)d_in[12];
    const float* trans   = (const float*)d_in[13];
    const float* fromB   = (const float*)d_in[14];
    const float* toE     = (const float*)d_in[15];
    float* out = (float*)d_out;

    const int lstm_smem = 65536 + 512 + 2048;   // ws + h_s + g_s = 68096 B
    cudaFuncSetAttribute(k_lstm, cudaFuncAttributeMaxDynamicSharedMemorySize, lstm_smem);

    k_gemm<<<dim3(TSEQ, 8), 256>>>(pad_seq, emb, Wihf, Wihb, bihf, bhhf, bihb, bhhb);
    k_lstm<<<BATCH, 512, lstm_smem>>>(lens, Whhf, Whhb);
    k_emis<<<(TSEQ * BATCH) / 8, 256>>>(Wlab, blab);
    k_vit<<<1, BATCH>>>(lens, trans, fromB, toE, out);
}

// round 7
// speedup vs baseline: 1.5909x; 1.5909x over previous
#include <cuda_runtime.h>
#include <cuda_bf16.h>
#include <math.h>

// Problem constants
#define TSEQ 512
#define BATCH 128
#define DIMD 256
#define HID 128
#define G4 512      // 4*H
#define LBL 4
#define VOC 8000

typedef unsigned long long u64;

// ---------------- scratch (device globals; no allocation allowed) ----------------
__device__ float d_tab[(size_t)2 * VOC * G4];              // 33 MB: per-token input gates + biases
__device__ float d_hbuf[(size_t)TSEQ * BATCH * 2 * HID];   // 67 MB: [t][b][256] = concat(hf, hb)
__device__ float d_scores[(size_t)TSEQ * BATCH * LBL];     // 1 MB:  [t][b][4]

// ---------------- f32x2 packed math (register-only packing) ----------------
__device__ __forceinline__ u64 pack2(float x, float y) {
    u64 r; asm("mov.b64 %0, {%1,%2};" : "=l"(r) : "f"(x), "f"(y)); return r;
}
__device__ __forceinline__ float2 unpack2(u64 a) {
    float x, y; asm("mov.b64 {%0,%1}, %2;" : "=f"(x), "=f"(y) : "l"(a));
    return make_float2(x, y);
}
__device__ __forceinline__ void fma2(u64& d, u64 a, u64 b) {
    asm("fma.rn.f32x2 %0, %1, %2, %0;" : "+l"(d) : "l"(a), "l"(b));
}

__device__ __forceinline__ float sigm(float x) { return 1.f / (1.f + expf(-x)); }

// ============================================================================
// Kernel 1: vocabulary projection  tab[dir][v] = emb[v] @ W_ih^T + (b_ih+b_hh)
// Grid (63 m-tiles of 128 vocab rows, 8 n-tiles: 4 fwd + 4 bwd), 256 threads.
// 8.2x less compute than projecting all (t,b) positions.
// ============================================================================
__global__ void __launch_bounds__(256) k_proj(
    const float* __restrict__ emb,
    const float* __restrict__ Wihf, const float* __restrict__ Wihb,
    const float* __restrict__ bihf, const float* __restrict__ bhhf,
    const float* __restrict__ bihb, const float* __restrict__ bhhb)
{
    __shared__ float As[16][128];   // [k][m]  m = vocab row
    __shared__ float Bs[16][128];   // [k][n]  n = gate row

    const int tid = threadIdx.x;
    const int mt  = blockIdx.x;          // vocab tile (0..62)
    const int nt  = blockIdx.y;          // 0..7
    const int dir = nt >> 2;
    const int gbase = (nt & 3) * 128;
    const float* __restrict__ W = dir ? Wihb : Wihf;

    const int tx = tid & 15, ty = tid >> 4;
    u64 acc[8][4];
#pragma unroll
    for (int i = 0; i < 8; ++i)
#pragma unroll
        for (int p = 0; p < 4; ++p) acc[i][p] = pack2(0.f, 0.f);

    for (int kt = 0; kt < 16; ++kt) {
        const int k0 = kt * 16;
        for (int e = tid; e < 512; e += 256) {
            const int row = e >> 2;            // 0..127
            const int kq  = (e & 3) * 4;       // 0,4,8,12
            int v = mt * 128 + row; if (v >= VOC) v = VOC - 1;   // clamp (reads only)
            const float4 av = *reinterpret_cast<const float4*>(
                &emb[(size_t)v * DIMD + k0 + kq]);
            As[kq + 0][row] = av.x; As[kq + 1][row] = av.y;
            As[kq + 2][row] = av.z; As[kq + 3][row] = av.w;
            const float4 bv = *reinterpret_cast<const float4*>(
                &W[(size_t)(gbase + row) * DIMD + k0 + kq]);
            Bs[kq + 0][row] = bv.x; Bs[kq + 1][row] = bv.y;
            Bs[kq + 2][row] = bv.z; Bs[kq + 3][row] = bv.w;
        }
        __syncthreads();
#pragma unroll
        for (int kk = 0; kk < 16; ++kk) {
            const float4 a0 = *reinterpret_cast<const float4*>(&As[kk][ty * 8]);
            const float4 a1 = *reinterpret_cast<const float4*>(&As[kk][ty * 8 + 4]);
            const float4 w0 = *reinterpret_cast<const float4*>(&Bs[kk][tx * 8]);
            const float4 w1 = *reinterpret_cast<const float4*>(&Bs[kk][tx * 8 + 4]);
            const u64 b0 = pack2(w0.x, w0.y);
            const u64 b1 = pack2(w0.z, w0.w);
            const u64 b2 = pack2(w1.x, w1.y);
            const u64 b3 = pack2(w1.z, w1.w);
            const float ar[8] = {a0.x, a0.y, a0.z, a0.w, a1.x, a1.y, a1.z, a1.w};
#pragma unroll
            for (int i = 0; i < 8; ++i) {
                const u64 ai = pack2(ar[i], ar[i]);
                fma2(acc[i][0], ai, b0);
                fma2(acc[i][1], ai, b1);
                fma2(acc[i][2], ai, b2);
                fma2(acc[i][3], ai, b3);
            }
        }
        __syncthreads();
    }

    const float* bi = dir ? bihb : bihf;
    const float* bh = dir ? bhhb : bhhf;
    float bias[8];
#pragma unroll
    for (int jj = 0; jj < 8; ++jj) {
        const int g = gbase + tx * 8 + jj;
        bias[jj] = bi[g] + bh[g];
    }
#pragma unroll
    for (int i = 0; i < 8; ++i) {
        const int v = mt * 128 + ty * 8 + i;
        if (v < VOC) {
            float* o = d_tab + (size_t)dir * ((size_t)VOC * G4)
                     + (size_t)v * G4 + gbase + tx * 8;
            const float2 v0 = unpack2(acc[i][0]);
            const float2 v1 = unpack2(acc[i][1]);
            const float2 v2 = unpack2(acc[i][2]);
            const float2 v3 = unpack2(acc[i][3]);
            float4 o0 = {v0.x + bias[0], v0.y + bias[1], v1.x + bias[2], v1.y + bias[3]};
            float4 o1 = {v2.x + bias[4], v2.y + bias[5], v3.x + bias[6], v3.y + bias[7]};
            *reinterpret_cast<float4*>(o)     = o0;
            *reinterpret_cast<float4*>(o + 4) = o1;
        }
    }
}

// ============================================================================
// Kernel 2: bidirectional LSTM recurrence. One block per batch element.
// 512 threads: thread j owns gate row j of W_hh [512,128].
// xg comes from the vocab projection table via token gather (prefetched one
// full step ahead). Weight split: 48 u64 in regs, 16 u64-slots in shared.
// ============================================================================
__global__ void __launch_bounds__(512, 1) k_lstm(
    const int* __restrict__ pad_seq, const int* __restrict__ lens,
    const float* __restrict__ Whhf, const float* __restrict__ Whhb)
{
    extern __shared__ char smp[];
    u64*   ws   = reinterpret_cast<u64*>(smp);                 // 16*512 u64 = 65536 B
    float* h_s  = reinterpret_cast<float*>(smp + 65536);       // 128 floats
    float* g_s  = reinterpret_cast<float*>(smp + 65536 + 512); // 512 floats
    int*   toks = reinterpret_cast<int*>(smp + 65536 + 512 + 2048); // 512 ints

    const int j = threadIdx.x;
    const int b = blockIdx.x;
    const int len = lens[b];

    toks[j] = pad_seq[b * TSEQ + j];    // whole token row for this batch elem

    for (int dir = 0; dir < 2; ++dir) {
        const float* __restrict__ wrow = (dir ? Whhb : Whhf) + (size_t)j * HID;
        u64 wr[48];
#pragma unroll
        for (int p = 0; p < 48; ++p) {
            const float2 w = *reinterpret_cast<const float2*>(wrow + 2 * p);
            wr[p] = pack2(w.x, w.y);                          // cols 0..95
        }
#pragma unroll
        for (int p = 0; p < 16; ++p) {
            const float2 w = *reinterpret_cast<const float2*>(wrow + 96 + 2 * p);
            ws[p * 512 + j] = pack2(w.x, w.y);                // cols 96..127
        }
        if (j < HID) h_s[j] = 0.f;
        float c = 0.f;
        __syncthreads();                 // covers toks + ws + h_s

        const float* __restrict__ tab = d_tab + (size_t)dir * ((size_t)VOC * G4) + j;
        int t = dir ? (TSEQ - 1) : 0;
        const int stp = dir ? -1 : 1;
        float xg = tab[(size_t)toks[t] * G4];

        for (int it = 0; it < TSEQ; ++it) {
            const int tn = t + stp;
            float xgn = 0.f;
            if (it < TSEQ - 1) xgn = tab[(size_t)toks[tn] * G4];   // prefetch next row

            u64 acc = pack2(xg, 0.f);
            const float4* h4 = reinterpret_cast<const float4*>(h_s);
#pragma unroll
            for (int q = 0; q < 24; ++q) {          // cols 0..95 from registers
                const float4 hv = h4[q];
                fma2(acc, wr[2 * q],     pack2(hv.x, hv.y));
                fma2(acc, wr[2 * q + 1], pack2(hv.z, hv.w));
            }
#pragma unroll
            for (int q = 0; q < 8; ++q) {           // cols 96..127 from shared
                const float4 hv = h4[24 + q];
                fma2(acc, ws[(2 * q) * 512 + j],     pack2(hv.x, hv.y));
                fma2(acc, ws[(2 * q + 1) * 512 + j], pack2(hv.z, hv.w));
            }
            const float2 av = unpack2(acc);
            g_s[j] = av.x + av.y;
            __syncthreads();

            if (j < HID) {
                const float gi = g_s[j];
                const float gf = g_s[j + 128];
                const float gc = g_s[j + 256];
                const float go = g_s[j + 384];
                const float i_ = sigm(gi);
                const float f_ = sigm(gf);
                const float o_ = sigm(go);
                const float c2 = f_ * c + i_ * tanhf(gc);
                const float h2 = o_ * tanhf(c2);
                const bool m = (t < len);
                d_hbuf[((size_t)t * BATCH + b) * (2 * HID) + dir * HID + j] = m ? h2 : 0.f;
                if (m) { c = c2; h_s[j] = h2; }
            }
            __syncthreads();
            xg = xgn;
            t = tn;
        }
        __syncthreads();   // protect ws/h_s reinit for next direction
    }
}

// ============================================================================
// Kernel 3: emissions  scores[t][b][l] = h[t][b][:] @ W_lab[l][:] + b_lab[l]
// ============================================================================
__global__ void __launch_bounds__(256) k_emis(
    const float* __restrict__ Wlab, const float* __restrict__ blab)
{
    __shared__ float wl[LBL * DIMD];
    const int tid = threadIdx.x;
    for (int e = tid; e < LBL * DIMD; e += 256) wl[e] = Wlab[e];
    __syncthreads();

    const int wid = tid >> 5, lane = tid & 31;
    const int m = blockIdx.x * 8 + wid;        // m = t*128 + b
    const float* h = d_hbuf + (size_t)m * (2 * HID);

    float a0 = 0.f, a1 = 0.f, a2 = 0.f, a3 = 0.f;
#pragma unroll
    for (int cch = 0; cch < 2; ++cch) {
        const int k = cch * 128 + lane * 4;
        const float4 hv = *reinterpret_cast<const float4*>(h + k);
        a0 += hv.x * wl[k]       + hv.y * wl[k + 1]       + hv.z * wl[k + 2]       + hv.w * wl[k + 3];
        a1 += hv.x * wl[256 + k] + hv.y * wl[256 + k + 1] + hv.z * wl[256 + k + 2] + hv.w * wl[256 + k + 3];
        a2 += hv.x * wl[512 + k] + hv.y * wl[512 + k + 1] + hv.z * wl[512 + k + 2] + hv.w * wl[512 + k + 3];
        a3 += hv.x * wl[768 + k] + hv.y * wl[768 + k + 1] + hv.z * wl[768 + k + 2] + hv.w * wl[768 + k + 3];
    }
#pragma unroll
    for (int off = 16; off; off >>= 1) {
        a0 += __shfl_down_sync(0xffffffffu, a0, off);
        a1 += __shfl_down_sync(0xffffffffu, a1, off);
        a2 += __shfl_down_sync(0xffffffffu, a2, off);
        a3 += __shfl_down_sync(0xffffffffu, a3, off);
    }
    if (lane == 0) {
        float4 o = {a0 + blab[0], a1 + blab[1], a2 + blab[2], a3 + blab[3]};
        *reinterpret_cast<float4*>(d_scores + (size_t)m * 4) = o;
    }
}

// ============================================================================
// Kernel 4: Viterbi forward + backtrace, smem-staged.
// 8 blocks x 128 threads; block handles 16 consecutive batch elements.
// Scores staged into shared (128 KB), backtrace kept in shared (32 KB),
// labels written back coalesced. Scan itself runs on 16 threads from smem.
// ============================================================================
__global__ void __launch_bounds__(128) k_vit(
    const int* __restrict__ lens, const float* __restrict__ trans,
    const float* __restrict__ fromB, const float* __restrict__ toE,
    float* __restrict__ out)
{
    extern __shared__ char vsm[];
    float*    s_sc  = reinterpret_cast<float*>(vsm);                  // 512*16*4 = 131072 B
    unsigned* s_bt  = reinterpret_cast<unsigned*>(vsm + 131072);      // 512*16*4 = 32768 B
    float*    s_lab = reinterpret_cast<float*>(vsm + 131072 + 32768); // 512*16*4 = 32768 B

    __shared__ float tr[16], fb[4], te[4];
    const int tid = threadIdx.x;
    const int b0 = blockIdx.x * 16;
    if (tid < 16) tr[tid] = trans[tid];
    if (tid < 4) { fb[tid] = fromB[tid]; te[tid] = toE[tid]; }

    // stage scores: s_sc[(t*16+bl)*4 + l]
    for (int e = tid; e < TSEQ * 16; e += 128) {
        const int t = e >> 4, bl = e & 15;
        const float4 v = *reinterpret_cast<const float4*>(
            d_scores + ((size_t)t * BATCH + b0 + bl) * 4);
        *reinterpret_cast<float4*>(s_sc + (size_t)e * 4) = v;
    }
    __syncthreads();

    if (tid < 16) {
        const int bl = tid;
        const int len = lens[b0 + bl];

        float best[4];
        {
            const float4 e0 = *reinterpret_cast<const float4*>(s_sc + bl * 4);
            best[0] = fb[0] + e0.x; best[1] = fb[1] + e0.y;
            best[2] = fb[2] + e0.z; best[3] = fb[3] + e0.w;
        }
        // ---- forward ----
        for (int t = 1; t < TSEQ; ++t) {
            const float4 ev = *reinterpret_cast<const float4*>(s_sc + (t * 16 + bl) * 4);
            const float e[4] = {ev.x, ev.y, ev.z, ev.w};
            unsigned w = 0;
            float nb[4];
#pragma unroll
            for (int l = 0; l < 4; ++l) {
                float mx = best[0] + tr[l];
                int ar = 0;
#pragma unroll
                for (int p = 1; p < 4; ++p) {
                    const float v = best[p] + tr[p * 4 + l];
                    if (v > mx) { mx = v; ar = p; }
                }
                nb[l] = mx + e[l];
                w |= (unsigned)ar << (2 * l);
            }
            s_bt[t * 16 + bl] = w;
            if (t < len) { best[0] = nb[0]; best[1] = nb[1]; best[2] = nb[2]; best[3] = nb[3]; }
        }
        // ---- terminal ----
        const float fv[4] = {best[0] + te[0], best[1] + te[1], best[2] + te[2], best[3] + te[3]};
        int last = 0; float bm = fv[0];
#pragma unroll
        for (int l = 1; l < 4; ++l) if (fv[l] > bm) { bm = fv[l]; last = l; }

        // ---- backtrace ----
        int lab = last;
        for (int t = TSEQ - 1; t >= 0; --t) {
            float v;
            if (t >= len) v = 0.f;
            else if (t == len - 1) { lab = last; v = (float)lab; }
            else { lab = (int)((s_bt[(t + 1) * 16 + bl] >> (2 * lab)) & 3u); v = (float)lab; }
            s_lab[t * 16 + bl] = v;
        }
    }
    __syncthreads();

    // coalesced output write: out[b][t]
    for (int e = tid; e < TSEQ * 16; e += 128) {
        const int bl = e >> 9, t = e & 511;
        out[(size_t)(b0 + bl) * TSEQ + t] = s_lab[t * 16 + bl];
    }
}

// ============================================================================
extern "C" void kernel_launch(void* const* d_in, const int* in_sizes, int n_in,
                              void* d_out, int out_size)
{
    const int*   pad_seq = (const int*)  d_in[0];
    const int*   lens    = (const int*)  d_in[1];
    const float* emb     = (const float*)d_in[2];
    const float* Wihf    = (const float*)d_in[3];
    const float* Whhf    = (const float*)d_in[4];
    const float* bihf    = (const float*)d_in[5];
    const float* bhhf    = (const float*)d_in[6];
    const float* Wihb    = (const float*)d_in[7];
    const float* Whhb    = (const float*)d_in[8];
    const float* bihb    = (const float*)d_in[9];
    const float* bhhb    = (const float*)d_in[10];
    const float* Wlab    = (const float*)d_in[11];
    const float* blab    = (const float*)d_in[12];
    const float* trans   = (const float*)d_in[13];
    const float* fromB   = (const float*)d_in[14];
    const float* toE     = (const float*)d_in[15];
    float* out = (float*)d_out;

    const int lstm_smem = 65536 + 512 + 2048 + 2048;   // ws + h_s + g_s + toks
    cudaFuncSetAttribute(k_lstm, cudaFuncAttributeMaxDynamicSharedMemorySize, lstm_smem);
    const int vit_smem = 131072 + 32768 + 32768;        // s_sc + s_bt + s_lab = 196608
    cudaFuncSetAttribute(k_vit, cudaFuncAttributeMaxDynamicSharedMemorySize, vit_smem);

    k_proj<<<dim3(63, 8), 256>>>(emb, Wihf, Wihb, bihf, bhhf, bihb, bhhb);
    k_lstm<<<BATCH, 512, lstm_smem>>>(pad_seq, lens, Whhf, Whhb);
    k_emis<<<(TSEQ * BATCH) / 8, 256>>>(Wlab, blab);
    k_vit<<<8, 128, vit_smem>>>(lens, trans, fromB, toE, out);
}

// round 8
// speedup vs baseline: 2.1850x; 1.3734x over previous
#include <cuda_runtime.h>
#include <cuda_bf16.h>
#include <math.h>

// Problem constants
#define TSEQ 512
#define BATCH 128
#define DIMD 256
#define HID 128
#define G4 512      // 4*H
#define LBL 4
#define VOC 8000

typedef unsigned long long u64;

// ---------------- scratch (device globals; no allocation allowed) ----------------
__device__ float d_tab[(size_t)2 * VOC * G4];              // 33 MB: per-token input gates + biases
__device__ float d_hbuf[(size_t)TSEQ * BATCH * 2 * HID];   // 67 MB: [t][b][256] = concat(hf, hb)
__device__ float d_scores[(size_t)TSEQ * BATCH * LBL];     // 1 MB:  [t][b][4]

// ---------------- f32x2 packed math (register-only packing) ----------------
__device__ __forceinline__ u64 pack2(float x, float y) {
    u64 r; asm("mov.b64 %0, {%1,%2};" : "=l"(r) : "f"(x), "f"(y)); return r;
}
__device__ __forceinline__ float2 unpack2(u64 a) {
    float x, y; asm("mov.b64 {%0,%1}, %2;" : "=f"(x), "=f"(y) : "l"(a));
    return make_float2(x, y);
}
__device__ __forceinline__ void fma2(u64& d, u64 a, u64 b) {
    asm("fma.rn.f32x2 %0, %1, %2, %0;" : "+l"(d) : "l"(a), "l"(b));
}

__device__ __forceinline__ float sigm(float x) { return 1.f / (1.f + expf(-x)); }

// ============================================================================
// Kernel 1: vocabulary projection  tab[dir][v] = emb[v] @ W_ih^T + (b_ih+b_hh)
// ============================================================================
__global__ void __launch_bounds__(256) k_proj(
    const float* __restrict__ emb,
    const float* __restrict__ Wihf, const float* __restrict__ Wihb,
    const float* __restrict__ bihf, const float* __restrict__ bhhf,
    const float* __restrict__ bihb, const float* __restrict__ bhhb)
{
    __shared__ float As[16][128];   // [k][m]  m = vocab row
    __shared__ float Bs[16][128];   // [k][n]  n = gate row

    const int tid = threadIdx.x;
    const int mt  = blockIdx.x;          // vocab tile (0..62)
    const int nt  = blockIdx.y;          // 0..7
    const int dir = nt >> 2;
    const int gbase = (nt & 3) * 128;
    const float* __restrict__ W = dir ? Wihb : Wihf;

    const int tx = tid & 15, ty = tid >> 4;
    u64 acc[8][4];
#pragma unroll
    for (int i = 0; i < 8; ++i)
#pragma unroll
        for (int p = 0; p < 4; ++p) acc[i][p] = pack2(0.f, 0.f);

    for (int kt = 0; kt < 16; ++kt) {
        const int k0 = kt * 16;
        for (int e = tid; e < 512; e += 256) {
            const int row = e >> 2;            // 0..127
            const int kq  = (e & 3) * 4;       // 0,4,8,12
            int v = mt * 128 + row; if (v >= VOC) v = VOC - 1;   // clamp (reads only)
            const float4 av = *reinterpret_cast<const float4*>(
                &emb[(size_t)v * DIMD + k0 + kq]);
            As[kq + 0][row] = av.x; As[kq + 1][row] = av.y;
            As[kq + 2][row] = av.z; As[kq + 3][row] = av.w;
            const float4 bv = *reinterpret_cast<const float4*>(
                &W[(size_t)(gbase + row) * DIMD + k0 + kq]);
            Bs[kq + 0][row] = bv.x; Bs[kq + 1][row] = bv.y;
            Bs[kq + 2][row] = bv.z; Bs[kq + 3][row] = bv.w;
        }
        __syncthreads();
#pragma unroll
        for (int kk = 0; kk < 16; ++kk) {
            const float4 a0 = *reinterpret_cast<const float4*>(&As[kk][ty * 8]);
            const float4 a1 = *reinterpret_cast<const float4*>(&As[kk][ty * 8 + 4]);
            const float4 w0 = *reinterpret_cast<const float4*>(&Bs[kk][tx * 8]);
            const float4 w1 = *reinterpret_cast<const float4*>(&Bs[kk][tx * 8 + 4]);
            const u64 b0 = pack2(w0.x, w0.y);
            const u64 b1 = pack2(w0.z, w0.w);
            const u64 b2 = pack2(w1.x, w1.y);
            const u64 b3 = pack2(w1.z, w1.w);
            const float ar[8] = {a0.x, a0.y, a0.z, a0.w, a1.x, a1.y, a1.z, a1.w};
#pragma unroll
            for (int i = 0; i < 8; ++i) {
                const u64 ai = pack2(ar[i], ar[i]);
                fma2(acc[i][0], ai, b0);
                fma2(acc[i][1], ai, b1);
                fma2(acc[i][2], ai, b2);
                fma2(acc[i][3], ai, b3);
            }
        }
        __syncthreads();
    }

    const float* bi = dir ? bihb : bihf;
    const float* bh = dir ? bhhb : bhhf;
    float bias[8];
#pragma unroll
    for (int jj = 0; jj < 8; ++jj) {
        const int g = gbase + tx * 8 + jj;
        bias[jj] = bi[g] + bh[g];
    }
#pragma unroll
    for (int i = 0; i < 8; ++i) {
        const int v = mt * 128 + ty * 8 + i;
        if (v < VOC) {
            float* o = d_tab + (size_t)dir * ((size_t)VOC * G4)
                     + (size_t)v * G4 + gbase + tx * 8;
            const float2 v0 = unpack2(acc[i][0]);
            const float2 v1 = unpack2(acc[i][1]);
            const float2 v2 = unpack2(acc[i][2]);
            const float2 v3 = unpack2(acc[i][3]);
            float4 o0 = {v0.x + bias[0], v0.y + bias[1], v1.x + bias[2], v1.y + bias[3]};
            float4 o1 = {v2.x + bias[4], v2.y + bias[5], v3.x + bias[6], v3.y + bias[7]};
            *reinterpret_cast<float4*>(o)     = o0;
            *reinterpret_cast<float4*>(o + 4) = o1;
        }
    }
}

// ============================================================================
// Kernel 2: bidirectional LSTM recurrence. One block per batch element.
// 256 threads, thread j owns gate rows j and j+256 — every h broadcast load
// feeds TWO rows (halves LDS h-wavefronts vs 512-thread layout).
// Weights: cols 0..95 in regs (2x48 u64), cols 96..127 in smem (64 KB).
// Gate nonlinearities applied in the PARALLEL phase (bit-identical math);
// serial activation phase has a single tanhf.
// ============================================================================
__global__ void __launch_bounds__(256, 1) k_lstm(
    const int* __restrict__ pad_seq, const int* __restrict__ lens,
    const float* __restrict__ Whhf, const float* __restrict__ Whhb)
{
    extern __shared__ char smp[];
    u64*   ws   = reinterpret_cast<u64*>(smp);                 // 16*512 u64 = 65536 B
    float* h_s  = reinterpret_cast<float*>(smp + 65536);       // 128 floats
    float* g_s  = reinterpret_cast<float*>(smp + 65536 + 512); // 512 floats (activated gates)
    int*   toks = reinterpret_cast<int*>(smp + 65536 + 512 + 2048); // 512 ints

    const int j = threadIdx.x;          // 0..255
    const int b = blockIdx.x;
    const int len = lens[b];

    toks[j]       = pad_seq[b * TSEQ + j];
    toks[j + 256] = pad_seq[b * TSEQ + j + 256];

    for (int dir = 0; dir < 2; ++dir) {
        const float* __restrict__ W = dir ? Whhb : Whhf;
        const float* wrowA = W + (size_t)j * HID;            // row j
        const float* wrowB = W + (size_t)(j + 256) * HID;    // row j+256
        u64 wrA[48], wrB[48];
#pragma unroll
        for (int p = 0; p < 48; ++p) {
            const float2 wa = *reinterpret_cast<const float2*>(wrowA + 2 * p);
            wrA[p] = pack2(wa.x, wa.y);
            const float2 wb = *reinterpret_cast<const float2*>(wrowB + 2 * p);
            wrB[p] = pack2(wb.x, wb.y);
        }
#pragma unroll
        for (int p = 0; p < 16; ++p) {
            const float2 wa = *reinterpret_cast<const float2*>(wrowA + 96 + 2 * p);
            ws[p * 512 + j] = pack2(wa.x, wa.y);
            const float2 wb = *reinterpret_cast<const float2*>(wrowB + 96 + 2 * p);
            ws[p * 512 + j + 256] = pack2(wb.x, wb.y);
        }
        if (j < HID) h_s[j] = 0.f;
        float c = 0.f;
        __syncthreads();                 // covers toks + ws + h_s

        const float* __restrict__ tab = d_tab + (size_t)dir * ((size_t)VOC * G4);
        int t = dir ? (TSEQ - 1) : 0;
        const int stp = dir ? -1 : 1;
        float xgA = tab[(size_t)toks[t] * G4 + j];
        float xgB = tab[(size_t)toks[t] * G4 + j + 256];

        for (int it = 0; it < TSEQ; ++it) {
            const int tn = t + stp;
            float xgAn = 0.f, xgBn = 0.f;
            if (it < TSEQ - 1) {                          // prefetch next token row
                const size_t base = (size_t)toks[tn] * G4;
                xgAn = tab[base + j];
                xgBn = tab[base + j + 256];
            }

            u64 accA = pack2(xgA, 0.f);
            u64 accB = pack2(xgB, 0.f);
            const float4* h4 = reinterpret_cast<const float4*>(h_s);
#pragma unroll
            for (int q = 0; q < 24; ++q) {          // cols 0..95 from registers
                const float4 hv = h4[q];
                const u64 hxy = pack2(hv.x, hv.y);
                const u64 hzw = pack2(hv.z, hv.w);
                fma2(accA, wrA[2 * q],     hxy);
                fma2(accA, wrA[2 * q + 1], hzw);
                fma2(accB, wrB[2 * q],     hxy);
                fma2(accB, wrB[2 * q + 1], hzw);
            }
#pragma unroll
            for (int q = 0; q < 8; ++q) {           // cols 96..127 from shared
                const float4 hv = h4[24 + q];
                const u64 hxy = pack2(hv.x, hv.y);
                const u64 hzw = pack2(hv.z, hv.w);
                fma2(accA, ws[(2 * q) * 512 + j],           hxy);
                fma2(accA, ws[(2 * q + 1) * 512 + j],       hzw);
                fma2(accB, ws[(2 * q) * 512 + j + 256],     hxy);
                fma2(accB, ws[(2 * q + 1) * 512 + j + 256], hzw);
            }
            const float2 avA = unpack2(accA);
            const float2 avB = unpack2(accB);
            const float gA = avA.x + avA.y;          // raw gate, row j     (i or f)
            const float gB = avB.x + avB.y;          // raw gate, row j+256 (g or o)
            // pre-activate: rows 0..255 are i/f (sigmoid); rows 256..383 are
            // cell-gate (tanh); rows 384..511 are o (sigmoid).
            g_s[j] = sigm(gA);
            g_s[j + 256] = (j < 128) ? tanhf(gB) : sigm(gB);
            __syncthreads();

            if (j < HID) {
                const float i_ = g_s[j];
                const float f_ = g_s[j + 128];
                const float tg = g_s[j + 256];
                const float o_ = g_s[j + 384];
                const float c2 = f_ * c + i_ * tg;
                const float h2 = o_ * tanhf(c2);
                const bool m = (t < len);
                d_hbuf[((size_t)t * BATCH + b) * (2 * HID) + dir * HID + j] = m ? h2 : 0.f;
                if (m) { c = c2; h_s[j] = h2; }
            }
            __syncthreads();
            xgA = xgAn; xgB = xgBn;
            t = tn;
        }
        __syncthreads();   // protect ws/h_s reinit for next direction
    }
}

// ============================================================================
// Kernel 3: emissions  scores[t][b][l] = h[t][b][:] @ W_lab[l][:] + b_lab[l]
// ============================================================================
__global__ void __launch_bounds__(256) k_emis(
    const float* __restrict__ Wlab, const float* __restrict__ blab)
{
    __shared__ float wl[LBL * DIMD];
    const int tid = threadIdx.x;
    for (int e = tid; e < LBL * DIMD; e += 256) wl[e] = Wlab[e];
    __syncthreads();

    const int wid = tid >> 5, lane = tid & 31;
    const int m = blockIdx.x * 8 + wid;        // m = t*128 + b
    const float* h = d_hbuf + (size_t)m * (2 * HID);

    float a0 = 0.f, a1 = 0.f, a2 = 0.f, a3 = 0.f;
#pragma unroll
    for (int cch = 0; cch < 2; ++cch) {
        const int k = cch * 128 + lane * 4;
        const float4 hv = *reinterpret_cast<const float4*>(h + k);
        a0 += hv.x * wl[k]       + hv.y * wl[k + 1]       + hv.z * wl[k + 2]       + hv.w * wl[k + 3];
        a1 += hv.x * wl[256 + k] + hv.y * wl[256 + k + 1] + hv.z * wl[256 + k + 2] + hv.w * wl[256 + k + 3];
        a2 += hv.x * wl[512 + k] + hv.y * wl[512 + k + 1] + hv.z * wl[512 + k + 2] + hv.w * wl[512 + k + 3];
        a3 += hv.x * wl[768 + k] + hv.y * wl[768 + k + 1] + hv.z * wl[768 + k + 2] + hv.w * wl[768 + k + 3];
    }
#pragma unroll
    for (int off = 16; off; off >>= 1) {
        a0 += __shfl_down_sync(0xffffffffu, a0, off);
        a1 += __shfl_down_sync(0xffffffffu, a1, off);
        a2 += __shfl_down_sync(0xffffffffu, a2, off);
        a3 += __shfl_down_sync(0xffffffffu, a3, off);
    }
    if (lane == 0) {
        float4 o = {a0 + blab[0], a1 + blab[1], a2 + blab[2], a3 + blab[3]};
        *reinterpret_cast<float4*>(d_scores + (size_t)m * 4) = o;
    }
}

// ============================================================================
// Kernel 4: Viterbi. One block per batch element (128 blocks x 128 threads).
// Scores staged to smem, single-thread scan+backtrace, coalesced write-back.
// ============================================================================
__global__ void __launch_bounds__(128) k_vit(
    const int* __restrict__ lens, const float* __restrict__ trans,
    const float* __restrict__ fromB, const float* __restrict__ toE,
    float* __restrict__ out)
{
    __shared__ float    s_sc[TSEQ * 4];     // 8 KB
    __shared__ unsigned s_bt[TSEQ];         // 2 KB
    __shared__ float    s_lab[TSEQ];        // 2 KB
    __shared__ float    tr[16], fb[4], te[4];

    const int tid = threadIdx.x;
    const int b = blockIdx.x;
    if (tid < 16) tr[tid] = trans[tid];
    if (tid < 4) { fb[tid] = fromB[tid]; te[tid] = toE[tid]; }

    // stage this batch element's scores: s_sc[t*4 + l]
#pragma unroll
    for (int u = 0; u < 4; ++u) {
        const int t = tid + u * 128;
        const float4 v = *reinterpret_cast<const float4*>(
            d_scores + ((size_t)t * BATCH + b) * 4);
        *reinterpret_cast<float4*>(s_sc + t * 4) = v;
    }
    __syncthreads();

    if (tid == 0) {
        const int len = lens[b];
        float best[4];
        {
            const float4 e0 = *reinterpret_cast<const float4*>(s_sc);
            best[0] = fb[0] + e0.x; best[1] = fb[1] + e0.y;
            best[2] = fb[2] + e0.z; best[3] = fb[3] + e0.w;
        }
        // ---- forward ----
        for (int t = 1; t < TSEQ; ++t) {
            const float4 ev = *reinterpret_cast<const float4*>(s_sc + t * 4);
            const float e[4] = {ev.x, ev.y, ev.z, ev.w};
            unsigned w = 0;
            float nb[4];
#pragma unroll
            for (int l = 0; l < 4; ++l) {
                float mx = best[0] + tr[l];
                int ar = 0;
#pragma unroll
                for (int p = 1; p < 4; ++p) {
                    const float v = best[p] + tr[p * 4 + l];
                    if (v > mx) { mx = v; ar = p; }
                }
                nb[l] = mx + e[l];
                w |= (unsigned)ar << (2 * l);
            }
            s_bt[t] = w;
            if (t < len) { best[0] = nb[0]; best[1] = nb[1]; best[2] = nb[2]; best[3] = nb[3]; }
        }
        // ---- terminal ----
        const float fv[4] = {best[0] + te[0], best[1] + te[1], best[2] + te[2], best[3] + te[3]};
        int last = 0; float bm = fv[0];
#pragma unroll
        for (int l = 1; l < 4; ++l) if (fv[l] > bm) { bm = fv[l]; last = l; }

        // ---- backtrace ----
        int lab = last;
        for (int t = TSEQ - 1; t >= 0; --t) {
            float v;
            if (t >= len) v = 0.f;
            else if (t == len - 1) { lab = last; v = (float)lab; }
            else { lab = (int)((s_bt[t + 1] >> (2 * lab)) & 3u); v = (float)lab; }
            s_lab[t] = v;
        }
    }
    __syncthreads();

    // coalesced write: out[b][t], float4 per thread
    {
        const float4* sl = reinterpret_cast<const float4*>(s_lab);
        float4* ob = reinterpret_cast<float4*>(out + (size_t)b * TSEQ);
        ob[tid] = sl[tid];
    }
}

// ============================================================================
extern "C" void kernel_launch(void* const* d_in, const int* in_sizes, int n_in,
                              void* d_out, int out_size)
{
    const int*   pad_seq = (const int*)  d_in[0];
    const int*   lens    = (const int*)  d_in[1];
    const float* emb     = (const float*)d_in[2];
    const float* Wihf    = (const float*)d_in[3];
    const float* Whhf    = (const float*)d_in[4];
    const float* bihf    = (const float*)d_in[5];
    const float* bhhf    = (const float*)d_in[6];
    const float* Wihb    = (const float*)d_in[7];
    const float* Whhb    = (const float*)d_in[8];
    const float* bihb    = (const float*)d_in[9];
    const float* bhhb    = (const float*)d_in[10];
    const float* Wlab    = (const float*)d_in[11];
    const float* blab    = (const float*)d_in[12];
    const float* trans   = (const float*)d_in[13];
    const float* fromB   = (const float*)d_in[14];
    const float* toE     = (const float*)d_in[15];
    float* out = (float*)d_out;

    const int lstm_smem = 65536 + 512 + 2048 + 2048;   // ws + h_s + g_s + toks = 70144
    cudaFuncSetAttribute(k_lstm, cudaFuncAttributeMaxDynamicSharedMemorySize, lstm_smem);

    k_proj<<<dim3(63, 8), 256>>>(emb, Wihf, Wihb, bihf, bhhf, bihb, bhhb);
    k_lstm<<<BATCH, 256, lstm_smem>>>(pad_seq, lens, Whhf, Whhb);
    k_emis<<<(TSEQ * BATCH) / 8, 256>>>(Wlab, blab);
    k_vit<<<BATCH, 128>>>(lens, trans, fromB, toE, out);
}